// round 9
// baseline (speedup 1.0000x reference)
#include <cuda_runtime.h>
#include <cuda_bf16.h>
#include <cuda_fp16.h>
#include <cstdint>

// Problem constants
#define BATCH 4
#define SEQ   2048
#define CH    1024
#define HEADS 16
#define HD    64
#define QSCALE 0.18033688011112042f   // 0.125 * log2(e)
#define LOG2E  1.4426950408889634f

// ---------------------------------------------------------------------------
// Scratch (allocation-free: __device__ globals)
// ---------------------------------------------------------------------------
__device__ __align__(16) __half g_qh[BATCH * HEADS * SEQ * HD];
__device__ __align__(16) __half g_ql[BATCH * HEADS * SEQ * HD];
__device__ __align__(16) __half g_kf[BATCH * HEADS * SEQ * HD];
__device__ __align__(16) __half g_vf[BATCH * HEADS * SEQ * HD];

__device__ __align__(16) __nv_bfloat16 g_xhi[8192 * 1024];
__device__ __align__(16) __nv_bfloat16 g_xlo[8192 * 1024];
__device__ __align__(16) __nv_bfloat16 g_wqh[3072 * 1024];
__device__ __align__(16) __nv_bfloat16 g_wql[3072 * 1024];
__device__ __align__(16) __nv_bfloat16 g_wph[1024 * 1024];
__device__ __align__(16) __nv_bfloat16 g_wpl[1024 * 1024];
__device__ __align__(16) __nv_bfloat16 g_aoh[8192 * 1024];
__device__ __align__(16) __nv_bfloat16 g_aol[8192 * 1024];

// ---------------------------------------------------------------------------
// Warp-MMA helpers (portable sm_80+ path; tcgen05 rejected by sm_100 target)
// ---------------------------------------------------------------------------
__device__ __forceinline__ uint32_t smem_u32(const void* p) {
    uint32_t a;
    asm("{ .reg .u64 t; cvta.to.shared.u64 t, %1; cvt.u32.u64 %0, t; }"
        : "=r"(a) : "l"(p));
    return a;
}

__device__ __forceinline__ void ldsm_x4(uint32_t addr, uint32_t& r0, uint32_t& r1,
                                        uint32_t& r2, uint32_t& r3) {
    asm volatile("ldmatrix.sync.aligned.m8n8.x4.shared.b16 {%0,%1,%2,%3}, [%4];"
                 : "=r"(r0), "=r"(r1), "=r"(r2), "=r"(r3) : "r"(addr));
}

__device__ __forceinline__ void ldsm_x4_t(uint32_t addr, uint32_t& r0, uint32_t& r1,
                                          uint32_t& r2, uint32_t& r3) {
    asm volatile("ldmatrix.sync.aligned.m8n8.x4.trans.shared.b16 {%0,%1,%2,%3}, [%4];"
                 : "=r"(r0), "=r"(r1), "=r"(r2), "=r"(r3) : "r"(addr));
}

__device__ __forceinline__ void mma_bf16(float* d, const uint32_t* a,
                                         const uint32_t* b) {
    asm volatile(
        "mma.sync.aligned.m16n8k16.row.col.f32.bf16.bf16.f32 "
        "{%0,%1,%2,%3}, {%4,%5,%6,%7}, {%8,%9}, {%0,%1,%2,%3};"
        : "+f"(d[0]), "+f"(d[1]), "+f"(d[2]), "+f"(d[3])
        : "r"(a[0]), "r"(a[1]), "r"(a[2]), "r"(a[3]), "r"(b[0]), "r"(b[1]));
}

__device__ __forceinline__ void mma_f16(float* d, const uint32_t* a,
                                        const uint32_t* b) {
    asm volatile(
        "mma.sync.aligned.m16n8k16.row.col.f32.f16.f16.f32 "
        "{%0,%1,%2,%3}, {%4,%5,%6,%7}, {%8,%9}, {%0,%1,%2,%3};"
        : "+f"(d[0]), "+f"(d[1]), "+f"(d[2]), "+f"(d[3])
        : "r"(a[0]), "r"(a[1]), "r"(a[2]), "r"(a[3]), "r"(b[0]), "r"(b[1]));
}

__device__ __forceinline__ void cp16(uint32_t dst, const void* src) {
    asm volatile("cp.async.cg.shared.global [%0], [%1], 16;"
                 :: "r"(dst), "l"(src));
}

__device__ __forceinline__ uint32_t pack_h2(float a, float b) {
    __half2 h = __floats2half2_rn(a, b);
    return *reinterpret_cast<uint32_t*>(&h);
}

// exp2 on FMA pipe: magic-number round + degree-5 Taylor. x <= 0 expected.
__device__ __forceinline__ float exp2_poly(float x) {
    x = fmaxf(x, -126.0f);
    float z = x + 12582912.0f;            // 1.5*2^23: RN rounds x to integer
    float r = z - 12582912.0f;            // r = rint(x)
    float f = x - r;                      // f in [-0.5, 0.5]
    float p = 1.3333558146e-3f;
    p = fmaf(p, f, 9.6181291076e-3f);
    p = fmaf(p, f, 5.5504108665e-2f);
    p = fmaf(p, f, 2.4022650696e-1f);
    p = fmaf(p, f, 6.9314718056e-1f);
    p = fmaf(p, f, 1.0f);
    int e = __float_as_int(z) - 0x4B400000;     // integer r from magic mantissa
    return p * __int_as_float((e + 127) << 23);
}

// ---------------------------------------------------------------------------
// fp32 -> (bf16 hi, bf16 lo) split conversion. One float4 per thread.
// ---------------------------------------------------------------------------
__global__ __launch_bounds__(256) void split_kernel(const float* __restrict__ src,
                                                    __nv_bfloat16* __restrict__ hi,
                                                    __nv_bfloat16* __restrict__ lo) {
    int i = blockIdx.x * 256 + threadIdx.x;
    float4 v = ((const float4*)src)[i];
    __nv_bfloat16 h0 = __float2bfloat16(v.x);
    __nv_bfloat16 h1 = __float2bfloat16(v.y);
    __nv_bfloat16 h2 = __float2bfloat16(v.z);
    __nv_bfloat16 h3 = __float2bfloat16(v.w);
    __nv_bfloat16 l0 = __float2bfloat16(v.x - __bfloat162float(h0));
    __nv_bfloat16 l1 = __float2bfloat16(v.y - __bfloat162float(h1));
    __nv_bfloat16 l2 = __float2bfloat16(v.z - __bfloat162float(h2));
    __nv_bfloat16 l3 = __float2bfloat16(v.w - __bfloat162float(h3));
    ((__nv_bfloat162*)hi)[2 * i]     = __nv_bfloat162(h0, h1);
    ((__nv_bfloat162*)hi)[2 * i + 1] = __nv_bfloat162(h2, h3);
    ((__nv_bfloat162*)lo)[2 * i]     = __nv_bfloat162(l0, l1);
    ((__nv_bfloat162*)lo)[2 * i + 1] = __nv_bfloat162(l2, l3);
}

// ---------------------------------------------------------------------------
// mma.sync GEMM (bf16 3-term split), 3-stage cp.async pipeline.
// Block 128x128, 8 warps (2x4), warp tile 64x32, K chunk 32, 96 chunks.
// mode 0: qkv -> write fp16 Qh/Ql (scaled), Kf, Vf.  mode 1: out = D + bias.
// smem per stage: A[128][40] + B[128][40] bf16 = 20,480 B; 3 stages = 61,440 B.
// ---------------------------------------------------------------------------
#define LDSG 40
#define STG_HALVES 5120          // 128*40 halves per matrix
#define STG_BYTES  20480         // per stage (A+B)
#define GEMM_SMEM_BYTES 61440

__global__ __launch_bounds__(256) void gemm_mma(
    const __nv_bfloat16* __restrict__ Ahi, const __nv_bfloat16* __restrict__ Alo,
    const __nv_bfloat16* __restrict__ Bhi, const __nv_bfloat16* __restrict__ Blo,
    const float* __restrict__ bias, float* __restrict__ out, int mode) {
    extern __shared__ __align__(16) __nv_bfloat16 smp[];

    const int tid = threadIdx.x;
    const int wid = tid >> 5, lane = tid & 31;
    const int m0 = blockIdx.y * 128;
    const int n0 = blockIdx.x * 128;
    const int wm = (wid >> 2) * 64;
    const int wn = (wid & 3) * 32;

    float acc[4][4][4] = {};

    const __nv_bfloat16* Aps[3] = {Ahi, Ahi, Alo};
    const __nv_bfloat16* Bps[3] = {Bhi, Blo, Bhi};

    const uint32_t sb = smem_u32(smp);

    // cp.async staging: thread -> (row, 16B chunk). 512 transfers per matrix.
    const int srow = tid >> 1;                 // 0..127
    const int sco  = (tid & 1) * 16;           // 0 or 16 (halves)
    const uint32_t sdst = (srow * LDSG + sco) * 2;

    auto stage = [&](int cn, int buf) {
        const __nv_bfloat16* Ap = Aps[cn >> 5];
        const __nv_bfloat16* Bp = Bps[cn >> 5];
        int k0 = (cn & 31) * 32;
        uint32_t ab = sb + buf * STG_BYTES + sdst;
        const __nv_bfloat16* asrc = Ap + (size_t)(m0 + srow) * 1024 + k0 + sco;
        const __nv_bfloat16* bsrc = Bp + (size_t)(n0 + srow) * 1024 + k0 + sco;
        cp16(ab, asrc);
        cp16(ab + 16, asrc + 8);
        cp16(ab + STG_HALVES * 2, bsrc);
        cp16(ab + STG_HALVES * 2 + 16, bsrc + 8);
    };

    // ldmatrix relative offsets within a stage
    uint32_t a_rel[4], b_rel[2];
#pragma unroll
    for (int i = 0; i < 4; i++)
        a_rel[i] = ((wm + i * 16 + (lane & 15)) * LDSG + ((lane >> 4) << 3)) * 2;
#pragma unroll
    for (int p = 0; p < 2; p++)
        b_rel[p] = STG_HALVES * 2 +
            ((wn + p * 16 + ((lane >> 4) << 3) + (lane & 7)) * LDSG +
             (((lane >> 3) & 1) << 3)) * 2;

    // Prologue: stages 0 and 1 in flight
    stage(0, 0);
    asm volatile("cp.async.commit_group;" ::: "memory");
    stage(1, 1);
    asm volatile("cp.async.commit_group;" ::: "memory");

    for (int c = 0; c < 96; c++) {
        asm volatile("cp.async.wait_group 1;" ::: "memory");
        __syncthreads();

        if (c + 2 < 96) stage(c + 2, (c + 2) % 3);
        asm volatile("cp.async.commit_group;" ::: "memory");

        const uint32_t soff = sb + (c % 3) * STG_BYTES;
#pragma unroll
        for (int kk = 0; kk < 2; kk++) {
            uint32_t a[4][4], b[2][4];
#pragma unroll
            for (int i = 0; i < 4; i++)
                ldsm_x4(soff + a_rel[i] + kk * 32, a[i][0], a[i][1], a[i][2], a[i][3]);
#pragma unroll
            for (int p = 0; p < 2; p++)
                ldsm_x4(soff + b_rel[p] + kk * 32, b[p][0], b[p][1], b[p][2], b[p][3]);
#pragma unroll
            for (int i = 0; i < 4; i++)
#pragma unroll
                for (int j = 0; j < 4; j++)
                    mma_bf16(acc[i][j], a[i], &b[j >> 1][(j & 1) * 2]);
        }
        __syncthreads();
    }

    const int rl = lane >> 2;
    const int cl = (lane & 3) * 2;
#pragma unroll
    for (int i = 0; i < 4; i++) {
#pragma unroll
        for (int j = 0; j < 4; j++) {
#pragma unroll
            for (int pr = 0; pr < 2; pr++) {
                int r  = m0 + wm + i * 16 + rl + pr * 8;
                int cg = n0 + wn + j * 8 + cl;
                float2 v = make_float2(acc[i][j][pr * 2], acc[i][j][pr * 2 + 1]);
                if (mode == 0) {
                    int three = cg >> 10;
                    int h = (cg >> 6) & 15;
                    int hd = cg & 63;
                    int b_ = r >> 11, nn = r & 2047;
                    size_t off = (size_t)((b_ * 16 + h) * 2048 + nn) * 64 + hd;
                    if (three == 0) {
                        float sx = v.x * QSCALE, sy = v.y * QSCALE;
                        __half2 hh = __floats2half2_rn(sx, sy);
                        __half2 hl = __floats2half2_rn(sx - __low2float(hh),
                                                       sy - __high2float(hh));
                        *(__half2*)(g_qh + off) = hh;
                        *(__half2*)(g_ql + off) = hl;
                    } else if (three == 1) {
                        *(__half2*)(g_kf + off) = __floats2half2_rn(v.x, v.y);
                    } else {
                        *(__half2*)(g_vf + off) = __floats2half2_rn(v.x, v.y);
                    }
                } else {
                    v.x += bias[cg];
                    v.y += bias[cg + 1];
                    *(float2*)(out + (size_t)r * 1024 + cg) = v;
                }
            }
        }
    }
}

// ---------------------------------------------------------------------------
// mma.sync flash attention. Block = (bh, 64-query tile), 4 warps (16 rows each).
// S = (Qh+Ql)*K fp16 (2 passes), softmax in log2 domain (FMA-pipe exp2),
// O += P(fp16)*V(fp16). K/V double-buffered via cp.async.
// Epilogue writes bf16 hi/lo split of O directly (fuses the old ao split).
// smem: Qs[64][136] | bias[64] | {K[64][72],V[64][72]} x2  = 54,528 B dynamic.
// ---------------------------------------------------------------------------
#define QSTR 136
#define KSTR 72
#define SM_KV0 17664
#define KVBUF  18432
#define ATTN_SMEM_BYTES 54528

__device__ __forceinline__ void stage_kv(uint32_t kd, const __half* ksrc,
                                         const __half* vsrc, int tid) {
#pragma unroll
    for (int t = 0; t < 4; t++) {
        int idx = tid + 128 * t;
        int r = idx >> 3, u = idx & 7;
        cp16(kd + (r * KSTR + u * 8) * 2, ksrc + r * 64 + u * 8);
        cp16(kd + 9216 + (r * KSTR + u * 8) * 2, vsrc + r * 64 + u * 8);
    }
}

__global__ __launch_bounds__(128) void attn_mma(const float* __restrict__ mWin) {
    extern __shared__ char smem[];
    float* bias_s = (float*)(smem + 17408);

    const int tid = threadIdx.x;
    const int lane = tid & 31, w = tid >> 5;
    const int qt = blockIdx.x & 31;
    const int bh = blockIdx.x >> 5;
    const int b = bh >> 4, h = bh & 15;

    const __half* qh_g = g_qh + ((size_t)bh * 2048 + qt * 64) * 64;
    const __half* ql_g = g_ql + ((size_t)bh * 2048 + qt * 64) * 64;
    const __half* kf_g = g_kf + (size_t)bh * 2048 * 64;
    const __half* vf_g = g_vf + (size_t)bh * 2048 * 64;

    const uint32_t sbase = smem_u32(smem);

    // issue cp.async for key tile 0
    stage_kv(sbase + SM_KV0, kf_g, vf_g, tid);
    asm volatile("cp.async.commit_group;" ::: "memory");

    // stage Q ([Qh | Ql] rows of 128 halves)
#pragma unroll
    for (int t = 0; t < 8; t++) {
        int idx = tid + 128 * t;
        int r = idx >> 4, u = idx & 15;
        const __half* src = (u < 8) ? qh_g + r * 64 + u * 8
                                    : ql_g + r * 64 + (u - 8) * 8;
        *(uint4*)(smem + ((size_t)r * QSTR + u * 8) * 2) = *(const uint4*)src;
    }
    __syncthreads();

    // preload Q fragments (8 k-chunks x 4 regs)
    uint32_t aQ[8][4];
#pragma unroll
    for (int kc = 0; kc < 8; kc++) {
        uint32_t addr = sbase +
            ((w * 16 + (lane & 15)) * QSTR + kc * 16 + (lane >> 4) * 8) * 2;
        ldsm_x4(addr, aQ[kc][0], aQ[kc][1], aQ[kc][2], aQ[kc][3]);
    }

    // ldmatrix relative offsets
    uint32_t kb_rel[4], vb_rel[4];
#pragma unroll
    for (int p = 0; p < 4; p++)
        kb_rel[p] = ((p * 16 + ((lane >> 4) << 3) + (lane & 7)) * KSTR +
                     (((lane >> 3) & 1) << 3)) * 2;
#pragma unroll
    for (int dn = 0; dn < 4; dn++)
        vb_rel[dn] = ((((lane >> 3) & 1) * 8 + (lane & 7)) * KSTR +
                      dn * 16 + (lane >> 4) * 8) * 2;

    float accO[8][4] = {};
    float m_lo = -1e30f, m_hi = -1e30f, l_lo = 0.0f, l_hi = 0.0f;
    const int c2 = (lane & 3) * 2;

    for (int kt = 0; kt < 32; kt++) {
        const int buf = kt & 1;
        if (kt + 1 < 32) {
            stage_kv(sbase + SM_KV0 + (buf ^ 1) * KVBUF,
                     kf_g + (size_t)(kt + 1) * 64 * 64,
                     vf_g + (size_t)(kt + 1) * 64 * 64, tid);
            asm volatile("cp.async.commit_group;" ::: "memory");
            asm volatile("cp.async.wait_group 1;" ::: "memory");
        } else {
            asm volatile("cp.async.wait_group 0;" ::: "memory");
        }
        if (tid < 64)
            bias_s[tid] = (mWin[b * 2048 + kt * 64 + tid] * 100.0f - 100.0f) * LOG2E;
        __syncthreads();

        const uint32_t kbase = sbase + SM_KV0 + buf * KVBUF;
        const uint32_t vbase = kbase + 9216;

        // S = Qh*K + Ql*K
        float accS[8][4] = {};
#pragma unroll
        for (int dc = 0; dc < 4; dc++) {
#pragma unroll
            for (int p = 0; p < 4; p++) {
                uint32_t b0, b1, b2, b3;
                ldsm_x4(kbase + kb_rel[p] + dc * 32, b0, b1, b2, b3);
                uint32_t bb[2];
                bb[0] = b0; bb[1] = b1;
                mma_f16(accS[2 * p], aQ[dc], bb);
                mma_f16(accS[2 * p], aQ[dc + 4], bb);
                bb[0] = b2; bb[1] = b3;
                mma_f16(accS[2 * p + 1], aQ[dc], bb);
                mma_f16(accS[2 * p + 1], aQ[dc + 4], bb);
            }
        }

        // + key bias (log2 units)
#pragma unroll
        for (int j = 0; j < 8; j++) {
            float b0v = bias_s[8 * j + c2], b1v = bias_s[8 * j + c2 + 1];
            accS[j][0] += b0v; accS[j][1] += b1v;
            accS[j][2] += b0v; accS[j][3] += b1v;
        }

        // online softmax (rows r=lane>>2 and r+8)
        float mx0 = -1e30f, mx1 = -1e30f;
#pragma unroll
        for (int j = 0; j < 8; j++) {
            mx0 = fmaxf(mx0, fmaxf(accS[j][0], accS[j][1]));
            mx1 = fmaxf(mx1, fmaxf(accS[j][2], accS[j][3]));
        }
        mx0 = fmaxf(mx0, __shfl_xor_sync(0xffffffffu, mx0, 1));
        mx0 = fmaxf(mx0, __shfl_xor_sync(0xffffffffu, mx0, 2));
        mx1 = fmaxf(mx1, __shfl_xor_sync(0xffffffffu, mx1, 1));
        mx1 = fmaxf(mx1, __shfl_xor_sync(0xffffffffu, mx1, 2));
        float mn0 = fmaxf(m_lo, mx0), mn1 = fmaxf(m_hi, mx1);
        float cor0 = exp2_poly(m_lo - mn0), cor1 = exp2_poly(m_hi - mn1);
        m_lo = mn0; m_hi = mn1;

        float s0 = 0.0f, s1 = 0.0f;
#pragma unroll
        for (int j = 0; j < 8; j++) {
            accS[j][0] = exp2_poly(accS[j][0] - m_lo);
            accS[j][1] = exp2_poly(accS[j][1] - m_lo);
            accS[j][2] = exp2_poly(accS[j][2] - m_hi);
            accS[j][3] = exp2_poly(accS[j][3] - m_hi);
            s0 += accS[j][0] + accS[j][1];
            s1 += accS[j][2] + accS[j][3];
        }
        s0 += __shfl_xor_sync(0xffffffffu, s0, 1);
        s0 += __shfl_xor_sync(0xffffffffu, s0, 2);
        s1 += __shfl_xor_sync(0xffffffffu, s1, 1);
        s1 += __shfl_xor_sync(0xffffffffu, s1, 2);
        l_lo = l_lo * cor0 + s0;
        l_hi = l_hi * cor1 + s1;
#pragma unroll
        for (int j = 0; j < 8; j++) {
            accO[j][0] *= cor0; accO[j][1] *= cor0;
            accO[j][2] *= cor1; accO[j][3] *= cor1;
        }

        // pack P -> fp16 A-fragments (in registers)
        uint32_t ph[8][2];
#pragma unroll
        for (int j = 0; j < 8; j++) {
            ph[j][0] = pack_h2(accS[j][0], accS[j][1]);
            ph[j][1] = pack_h2(accS[j][2], accS[j][3]);
        }

        // O += P * V  (V via ldmatrix.trans)
#pragma unroll
        for (int kc = 0; kc < 4; kc++) {
            uint32_t a[4] = {ph[2 * kc][0], ph[2 * kc][1],
                             ph[2 * kc + 1][0], ph[2 * kc + 1][1]};
#pragma unroll
            for (int dn = 0; dn < 4; dn++) {
                uint32_t r0, r1, r2, r3;
                ldsm_x4_t(vbase + vb_rel[dn] + kc * 16 * KSTR * 2, r0, r1, r2, r3);
                uint32_t bb[2];
                bb[0] = r0; bb[1] = r1;
                mma_f16(accO[2 * dn], a, bb);
                bb[0] = r2; bb[1] = r3;
                mma_f16(accO[2 * dn + 1], a, bb);
            }
        }
        __syncthreads();
    }

    // epilogue: O / l -> bf16 hi/lo split, directly into proj GEMM inputs
    float i0 = 1.0f / l_lo, i1 = 1.0f / l_hi;
    int qn = qt * 64 + w * 16 + (lane >> 2);
    int col0 = h * 64 + c2;
#pragma unroll
    for (int j = 0; j < 8; j++) {
        size_t off0 = (size_t)(b * 2048 + qn) * 1024 + col0 + 8 * j;
        size_t off1 = (size_t)(b * 2048 + qn + 8) * 1024 + col0 + 8 * j;
        float x0 = accO[j][0] * i0, y0 = accO[j][1] * i0;
        float x1 = accO[j][2] * i1, y1 = accO[j][3] * i1;
        __nv_bfloat16 h00 = __float2bfloat16(x0), h01 = __float2bfloat16(y0);
        __nv_bfloat16 h10 = __float2bfloat16(x1), h11 = __float2bfloat16(y1);
        *(__nv_bfloat162*)(g_aoh + off0) = __nv_bfloat162(h00, h01);
        *(__nv_bfloat162*)(g_aol + off0) =
            __nv_bfloat162(__float2bfloat16(x0 - __bfloat162float(h00)),
                           __float2bfloat16(y0 - __bfloat162float(h01)));
        *(__nv_bfloat162*)(g_aoh + off1) = __nv_bfloat162(h10, h11);
        *(__nv_bfloat162*)(g_aol + off1) =
            __nv_bfloat162(__float2bfloat16(x1 - __bfloat162float(h10)),
                           __float2bfloat16(y1 - __bfloat162float(h11)));
    }
}

// ---------------------------------------------------------------------------
extern "C" void kernel_launch(void* const* d_in, const int* in_sizes, int n_in,
                              void* d_out, int out_size) {
    const float* x      = (const float*)d_in[0];
    const float* mWin   = (const float*)d_in[1];
    const float* w_qkv  = (const float*)d_in[2];
    const float* w_proj = (const float*)d_in[3];
    const float* b_proj = (const float*)d_in[4];
    float* out = (float*)d_out;

    __nv_bfloat16 *xhi, *xlo, *wqh, *wql, *wph, *wpl, *aoh, *aol;
    cudaGetSymbolAddress((void**)&xhi, g_xhi);
    cudaGetSymbolAddress((void**)&xlo, g_xlo);
    cudaGetSymbolAddress((void**)&wqh, g_wqh);
    cudaGetSymbolAddress((void**)&wql, g_wql);
    cudaGetSymbolAddress((void**)&wph, g_wph);
    cudaGetSymbolAddress((void**)&wpl, g_wpl);
    cudaGetSymbolAddress((void**)&aoh, g_aoh);
    cudaGetSymbolAddress((void**)&aol, g_aol);

    cudaFuncSetAttribute(gemm_mma, cudaFuncAttributeMaxDynamicSharedMemorySize,
                         GEMM_SMEM_BYTES);
    cudaFuncSetAttribute(attn_mma, cudaFuncAttributeMaxDynamicSharedMemorySize,
                         ATTN_SMEM_BYTES);

    // Split conversions (fp32 -> bf16 hi/lo)
    split_kernel<<<8192, 256>>>(x, xhi, xlo);
    split_kernel<<<3072, 256>>>(w_qkv, wqh, wql);
    split_kernel<<<1024, 256>>>(w_proj, wph, wpl);

    // QKV projection -> fp16 Qh/Ql (scaled), Kf, Vf
    gemm_mma<<<dim3(24, 64), 256, GEMM_SMEM_BYTES>>>(xhi, xlo, wqh, wql,
                                                     nullptr, nullptr, 0);

    // Flash attention (mma.sync fp16), writes aoh/aol directly
    attn_mma<<<2048, 128, ATTN_SMEM_BYTES>>>(mWin);

    // Output projection + bias
    gemm_mma<<<dim3(8, 64), 256, GEMM_SMEM_BYTES>>>(aoh, aol, wph, wpl,
                                                    b_proj, out, 1);
}

// round 10
// speedup vs baseline: 1.4965x; 1.4965x over previous
#include <cuda_runtime.h>
#include <cuda_fp16.h>
#include <cstdint>

// Problem constants
#define BATCH 4
#define SEQ   2048
#define CH    1024
#define HEADS 16
#define HD    64
#define QSCALE 0.18033688011112042f   // 0.125 * log2(e)
#define LOG2E  1.4426950408889634f

// ---------------------------------------------------------------------------
// Scratch (allocation-free: __device__ globals)
// ---------------------------------------------------------------------------
__device__ __align__(16) __half g_qh[BATCH * HEADS * SEQ * HD];  // Q*QSCALE fp16
__device__ __align__(16) __half g_kf[BATCH * HEADS * SEQ * HD];
__device__ __align__(16) __half g_vf[BATCH * HEADS * SEQ * HD];
__device__ __align__(16) __half g_of[8192 * 1024];               // attn output

__device__ __align__(16) __half g_xh [8192 * 1024];
__device__ __align__(16) __half g_wqh[3072 * 1024];
__device__ __align__(16) __half g_wql[3072 * 1024];
__device__ __align__(16) __half g_wph[1024 * 1024];
__device__ __align__(16) __half g_wpl[1024 * 1024];

// ---------------------------------------------------------------------------
// Warp-MMA helpers (portable sm_80+ path; tcgen05 rejected by sm_100 target)
// ---------------------------------------------------------------------------
__device__ __forceinline__ uint32_t smem_u32(const void* p) {
    uint32_t a;
    asm("{ .reg .u64 t; cvta.to.shared.u64 t, %1; cvt.u32.u64 %0, t; }"
        : "=r"(a) : "l"(p));
    return a;
}

__device__ __forceinline__ void ldsm_x4(uint32_t addr, uint32_t& r0, uint32_t& r1,
                                        uint32_t& r2, uint32_t& r3) {
    asm volatile("ldmatrix.sync.aligned.m8n8.x4.shared.b16 {%0,%1,%2,%3}, [%4];"
                 : "=r"(r0), "=r"(r1), "=r"(r2), "=r"(r3) : "r"(addr));
}

__device__ __forceinline__ void ldsm_x4_t(uint32_t addr, uint32_t& r0, uint32_t& r1,
                                          uint32_t& r2, uint32_t& r3) {
    asm volatile("ldmatrix.sync.aligned.m8n8.x4.trans.shared.b16 {%0,%1,%2,%3}, [%4];"
                 : "=r"(r0), "=r"(r1), "=r"(r2), "=r"(r3) : "r"(addr));
}

__device__ __forceinline__ void mma_f16(float* d, const uint32_t* a,
                                        const uint32_t* b) {
    asm volatile(
        "mma.sync.aligned.m16n8k16.row.col.f32.f16.f16.f32 "
        "{%0,%1,%2,%3}, {%4,%5,%6,%7}, {%8,%9}, {%0,%1,%2,%3};"
        : "+f"(d[0]), "+f"(d[1]), "+f"(d[2]), "+f"(d[3])
        : "r"(a[0]), "r"(a[1]), "r"(a[2]), "r"(a[3]), "r"(b[0]), "r"(b[1]));
}

__device__ __forceinline__ void cp16(uint32_t dst, const void* src) {
    asm volatile("cp.async.cg.shared.global [%0], [%1], 16;"
                 :: "r"(dst), "l"(src));
}

__device__ __forceinline__ uint32_t pack_h2(float a, float b) {
    __half2 h = __floats2half2_rn(a, b);
    return *reinterpret_cast<uint32_t*>(&h);
}

// exp2 on FMA pipe: magic-number round + degree-5 Taylor. x <= 0 expected.
__device__ __forceinline__ float exp2_poly(float x) {
    x = fmaxf(x, -126.0f);
    float z = x + 12582912.0f;            // 1.5*2^23: RN rounds x to integer
    float r = z - 12582912.0f;            // r = rint(x)
    float f = x - r;                      // f in [-0.5, 0.5]
    float p = 1.3333558146e-3f;
    p = fmaf(p, f, 9.6181291076e-3f);
    p = fmaf(p, f, 5.5504108665e-2f);
    p = fmaf(p, f, 2.4022650696e-1f);
    p = fmaf(p, f, 6.9314718056e-1f);
    p = fmaf(p, f, 1.0f);
    int e = __float_as_int(z) - 0x4B400000;     // integer r from magic mantissa
    return p * __int_as_float((e + 127) << 23);
}

// ---------------------------------------------------------------------------
// Conversions: fp32 -> fp16, and fp32 -> (fp16 hi, fp16 lo) split.
// ---------------------------------------------------------------------------
__global__ __launch_bounds__(256) void tofp16_kernel(const float* __restrict__ src,
                                                     __half* __restrict__ dst) {
    int i = blockIdx.x * 256 + threadIdx.x;
    float4 v = ((const float4*)src)[i];
    ((__half2*)dst)[2 * i]     = __floats2half2_rn(v.x, v.y);
    ((__half2*)dst)[2 * i + 1] = __floats2half2_rn(v.z, v.w);
}

__global__ __launch_bounds__(256) void splitf16_kernel(const float* __restrict__ src,
                                                       __half* __restrict__ hi,
                                                       __half* __restrict__ lo) {
    int i = blockIdx.x * 256 + threadIdx.x;
    float4 v = ((const float4*)src)[i];
    __half2 h0 = __floats2half2_rn(v.x, v.y);
    __half2 h1 = __floats2half2_rn(v.z, v.w);
    __half2 l0 = __floats2half2_rn(v.x - __low2float(h0), v.y - __high2float(h0));
    __half2 l1 = __floats2half2_rn(v.z - __low2float(h1), v.w - __high2float(h1));
    ((__half2*)hi)[2 * i]     = h0;
    ((__half2*)hi)[2 * i + 1] = h1;
    ((__half2*)lo)[2 * i]     = l0;
    ((__half2*)lo)[2 * i + 1] = l1;
}

// ---------------------------------------------------------------------------
// mma.sync GEMM: D = A * (Bh + Bl)^T, fp16, 2 MMA passes sharing one A tile.
// Block 128x128, 8 warps (2x4), warp tile 64x32, K chunk 32, 32 chunks,
// 2-stage cp.async pipeline. Stage = A + Bh + Bl = 30,720 B; 2 stages.
// mode 0: qkv -> write fp16 Qs (scaled), K, V.  mode 1: out = D + bias.
// ---------------------------------------------------------------------------
#define LDSG 40
#define MATB 10240                   // one 128x40 fp16 matrix, bytes
#define STGB 30720                   // stage bytes (A+Bh+Bl)
#define GEMM_SMEM_BYTES 61440

__global__ __launch_bounds__(256) void gemm_mma(
    const __half* __restrict__ A, const __half* __restrict__ Bh,
    const __half* __restrict__ Bl,
    const float* __restrict__ bias, float* __restrict__ out, int mode) {
    extern __shared__ __align__(16) __half smp[];

    const int tid = threadIdx.x;
    const int wid = tid >> 5, lane = tid & 31;
    const int m0 = blockIdx.y * 128;
    const int n0 = blockIdx.x * 128;
    const int wm = (wid >> 2) * 64;
    const int wn = (wid & 3) * 32;

    float acc[4][4][4] = {};

    const uint32_t sb = smem_u32(smp);

    // cp.async staging: thread -> (row, 32B half-row chunk)
    const int srow = tid >> 1;
    const int sco  = (tid & 1) * 16;               // halves
    const uint32_t sdst = (srow * LDSG + sco) * 2;

    auto stage = [&](int cn, int buf) {
        int k0 = cn * 32;
        uint32_t ab = sb + buf * STGB + sdst;
        const __half* as = A  + (size_t)(m0 + srow) * 1024 + k0 + sco;
        const __half* bh = Bh + (size_t)(n0 + srow) * 1024 + k0 + sco;
        const __half* bl = Bl + (size_t)(n0 + srow) * 1024 + k0 + sco;
        cp16(ab, as);               cp16(ab + 16, as + 8);
        cp16(ab + MATB, bh);        cp16(ab + MATB + 16, bh + 8);
        cp16(ab + 2 * MATB, bl);    cp16(ab + 2 * MATB + 16, bl + 8);
    };

    // ldmatrix relative offsets within a stage
    uint32_t a_rel[4], bh_rel[2];
#pragma unroll
    for (int i = 0; i < 4; i++)
        a_rel[i] = ((wm + i * 16 + (lane & 15)) * LDSG + ((lane >> 4) << 3)) * 2;
#pragma unroll
    for (int p = 0; p < 2; p++)
        bh_rel[p] = MATB +
            ((wn + p * 16 + ((lane >> 4) << 3) + (lane & 7)) * LDSG +
             (((lane >> 3) & 1) << 3)) * 2;

    stage(0, 0);
    asm volatile("cp.async.commit_group;" ::: "memory");

    for (int c = 0; c < 32; c++) {
        if (c + 1 < 32) {
            stage(c + 1, (c + 1) & 1);
            asm volatile("cp.async.commit_group;" ::: "memory");
            asm volatile("cp.async.wait_group 1;" ::: "memory");
        } else {
            asm volatile("cp.async.wait_group 0;" ::: "memory");
        }
        __syncthreads();

        const uint32_t soff = sb + (c & 1) * STGB;
#pragma unroll
        for (int kk = 0; kk < 2; kk++) {
            uint32_t a[4][4], b[2][4];
#pragma unroll
            for (int i = 0; i < 4; i++)
                ldsm_x4(soff + a_rel[i] + kk * 32, a[i][0], a[i][1], a[i][2], a[i][3]);
            // pass 1: Bh
#pragma unroll
            for (int p = 0; p < 2; p++)
                ldsm_x4(soff + bh_rel[p] + kk * 32, b[p][0], b[p][1], b[p][2], b[p][3]);
#pragma unroll
            for (int i = 0; i < 4; i++)
#pragma unroll
                for (int j = 0; j < 4; j++)
                    mma_f16(acc[i][j], a[i], &b[j >> 1][(j & 1) * 2]);
            // pass 2: Bl (same A)
#pragma unroll
            for (int p = 0; p < 2; p++)
                ldsm_x4(soff + bh_rel[p] + MATB + kk * 32,
                        b[p][0], b[p][1], b[p][2], b[p][3]);
#pragma unroll
            for (int i = 0; i < 4; i++)
#pragma unroll
                for (int j = 0; j < 4; j++)
                    mma_f16(acc[i][j], a[i], &b[j >> 1][(j & 1) * 2]);
        }
        __syncthreads();
    }

    const int rl = lane >> 2;
    const int cl = (lane & 3) * 2;
#pragma unroll
    for (int i = 0; i < 4; i++) {
#pragma unroll
        for (int j = 0; j < 4; j++) {
#pragma unroll
            for (int pr = 0; pr < 2; pr++) {
                int r  = m0 + wm + i * 16 + rl + pr * 8;
                int cg = n0 + wn + j * 8 + cl;
                float2 v = make_float2(acc[i][j][pr * 2], acc[i][j][pr * 2 + 1]);
                if (mode == 0) {
                    int three = cg >> 10;
                    int h = (cg >> 6) & 15;
                    int hd = cg & 63;
                    int b_ = r >> 11, nn = r & 2047;
                    size_t off = (size_t)((b_ * 16 + h) * 2048 + nn) * 64 + hd;
                    if (three == 0) {
                        *(__half2*)(g_qh + off) =
                            __floats2half2_rn(v.x * QSCALE, v.y * QSCALE);
                    } else if (three == 1) {
                        *(__half2*)(g_kf + off) = __floats2half2_rn(v.x, v.y);
                    } else {
                        *(__half2*)(g_vf + off) = __floats2half2_rn(v.x, v.y);
                    }
                } else {
                    v.x += bias[cg];
                    v.y += bias[cg + 1];
                    *(float2*)(out + (size_t)r * 1024 + cg) = v;
                }
            }
        }
    }
}

// ---------------------------------------------------------------------------
// mma.sync flash attention. Block = (bh, 64-query tile), 4 warps (16 rows each).
// S = Q*K fp16 (1 pass), softmax in log2 domain (FMA-pipe exp2),
// O += P(fp16)*V(fp16). K/V double-buffered via cp.async.
// Epilogue writes O as single fp16 (proj GEMM A input).
// smem: Qs[64][72] | bias[64] | {K[64][72],V[64][72]} x2  = 46,336 B dynamic.
// ---------------------------------------------------------------------------
#define QSTR 72
#define KSTR 72
#define SM_KV0 9472
#define KVBUF  18432
#define ATTN_SMEM_BYTES 46336

__device__ __forceinline__ void stage_kv(uint32_t kd, const __half* ksrc,
                                         const __half* vsrc, int tid) {
#pragma unroll
    for (int t = 0; t < 4; t++) {
        int idx = tid + 128 * t;
        int r = idx >> 3, u = idx & 7;
        cp16(kd + (r * KSTR + u * 8) * 2, ksrc + r * 64 + u * 8);
        cp16(kd + 9216 + (r * KSTR + u * 8) * 2, vsrc + r * 64 + u * 8);
    }
}

__global__ __launch_bounds__(128) void attn_mma(const float* __restrict__ mWin) {
    extern __shared__ char smem[];
    float* bias_s = (float*)(smem + 9216);

    const int tid = threadIdx.x;
    const int lane = tid & 31, w = tid >> 5;
    const int qt = blockIdx.x & 31;
    const int bh = blockIdx.x >> 5;
    const int b = bh >> 4, h = bh & 15;

    const __half* qh_g = g_qh + ((size_t)bh * 2048 + qt * 64) * 64;
    const __half* kf_g = g_kf + (size_t)bh * 2048 * 64;
    const __half* vf_g = g_vf + (size_t)bh * 2048 * 64;

    const uint32_t sbase = smem_u32(smem);

    // issue cp.async for key tile 0
    stage_kv(sbase + SM_KV0, kf_g, vf_g, tid);
    asm volatile("cp.async.commit_group;" ::: "memory");

    // stage Q (64 rows x 64 halves, stride 72)
#pragma unroll
    for (int t = 0; t < 4; t++) {
        int idx = tid + 128 * t;
        int r = idx >> 3, u = idx & 7;
        *(uint4*)(smem + ((size_t)r * QSTR + u * 8) * 2) =
            *(const uint4*)(qh_g + r * 64 + u * 8);
    }
    __syncthreads();

    // preload Q fragments (4 k-chunks x 4 regs)
    uint32_t aQ[4][4];
#pragma unroll
    for (int kc = 0; kc < 4; kc++) {
        uint32_t addr = sbase +
            ((w * 16 + (lane & 15)) * QSTR + kc * 16 + (lane >> 4) * 8) * 2;
        ldsm_x4(addr, aQ[kc][0], aQ[kc][1], aQ[kc][2], aQ[kc][3]);
    }

    // ldmatrix relative offsets
    uint32_t kb_rel[4], vb_rel[4];
#pragma unroll
    for (int p = 0; p < 4; p++)
        kb_rel[p] = ((p * 16 + ((lane >> 4) << 3) + (lane & 7)) * KSTR +
                     (((lane >> 3) & 1) << 3)) * 2;
#pragma unroll
    for (int dn = 0; dn < 4; dn++)
        vb_rel[dn] = ((((lane >> 3) & 1) * 8 + (lane & 7)) * KSTR +
                      dn * 16 + (lane >> 4) * 8) * 2;

    float accO[8][4] = {};
    float m_lo = -1e30f, m_hi = -1e30f, l_lo = 0.0f, l_hi = 0.0f;
    const int c2 = (lane & 3) * 2;

    for (int kt = 0; kt < 32; kt++) {
        const int buf = kt & 1;
        if (kt + 1 < 32) {
            stage_kv(sbase + SM_KV0 + (buf ^ 1) * KVBUF,
                     kf_g + (size_t)(kt + 1) * 64 * 64,
                     vf_g + (size_t)(kt + 1) * 64 * 64, tid);
            asm volatile("cp.async.commit_group;" ::: "memory");
            asm volatile("cp.async.wait_group 1;" ::: "memory");
        } else {
            asm volatile("cp.async.wait_group 0;" ::: "memory");
        }
        if (tid < 64)
            bias_s[tid] = (mWin[b * 2048 + kt * 64 + tid] * 100.0f - 100.0f) * LOG2E;
        __syncthreads();

        const uint32_t kbase = sbase + SM_KV0 + buf * KVBUF;
        const uint32_t vbase = kbase + 9216;

        // S = Q*K (single fp16 pass)
        float accS[8][4] = {};
#pragma unroll
        for (int dc = 0; dc < 4; dc++) {
#pragma unroll
            for (int p = 0; p < 4; p++) {
                uint32_t b0, b1, b2, b3;
                ldsm_x4(kbase + kb_rel[p] + dc * 32, b0, b1, b2, b3);
                uint32_t bb[2];
                bb[0] = b0; bb[1] = b1;
                mma_f16(accS[2 * p], aQ[dc], bb);
                bb[0] = b2; bb[1] = b3;
                mma_f16(accS[2 * p + 1], aQ[dc], bb);
            }
        }

        // + key bias (log2 units)
#pragma unroll
        for (int j = 0; j < 8; j++) {
            float b0v = bias_s[8 * j + c2], b1v = bias_s[8 * j + c2 + 1];
            accS[j][0] += b0v; accS[j][1] += b1v;
            accS[j][2] += b0v; accS[j][3] += b1v;
        }

        // online softmax (rows r=lane>>2 and r+8)
        float mx0 = -1e30f, mx1 = -1e30f;
#pragma unroll
        for (int j = 0; j < 8; j++) {
            mx0 = fmaxf(mx0, fmaxf(accS[j][0], accS[j][1]));
            mx1 = fmaxf(mx1, fmaxf(accS[j][2], accS[j][3]));
        }
        mx0 = fmaxf(mx0, __shfl_xor_sync(0xffffffffu, mx0, 1));
        mx0 = fmaxf(mx0, __shfl_xor_sync(0xffffffffu, mx0, 2));
        mx1 = fmaxf(mx1, __shfl_xor_sync(0xffffffffu, mx1, 1));
        mx1 = fmaxf(mx1, __shfl_xor_sync(0xffffffffu, mx1, 2));
        float mn0 = fmaxf(m_lo, mx0), mn1 = fmaxf(m_hi, mx1);
        float cor0 = exp2_poly(m_lo - mn0), cor1 = exp2_poly(m_hi - mn1);
        m_lo = mn0; m_hi = mn1;

        float s0 = 0.0f, s1 = 0.0f;
#pragma unroll
        for (int j = 0; j < 8; j++) {
            accS[j][0] = exp2_poly(accS[j][0] - m_lo);
            accS[j][1] = exp2_poly(accS[j][1] - m_lo);
            accS[j][2] = exp2_poly(accS[j][2] - m_hi);
            accS[j][3] = exp2_poly(accS[j][3] - m_hi);
            s0 += accS[j][0] + accS[j][1];
            s1 += accS[j][2] + accS[j][3];
        }
        s0 += __shfl_xor_sync(0xffffffffu, s0, 1);
        s0 += __shfl_xor_sync(0xffffffffu, s0, 2);
        s1 += __shfl_xor_sync(0xffffffffu, s1, 1);
        s1 += __shfl_xor_sync(0xffffffffu, s1, 2);
        l_lo = l_lo * cor0 + s0;
        l_hi = l_hi * cor1 + s1;
#pragma unroll
        for (int j = 0; j < 8; j++) {
            accO[j][0] *= cor0; accO[j][1] *= cor0;
            accO[j][2] *= cor1; accO[j][3] *= cor1;
        }

        // pack P -> fp16 A-fragments (in registers)
        uint32_t ph[8][2];
#pragma unroll
        for (int j = 0; j < 8; j++) {
            ph[j][0] = pack_h2(accS[j][0], accS[j][1]);
            ph[j][1] = pack_h2(accS[j][2], accS[j][3]);
        }

        // O += P * V  (V via ldmatrix.trans)
#pragma unroll
        for (int kc = 0; kc < 4; kc++) {
            uint32_t a[4] = {ph[2 * kc][0], ph[2 * kc][1],
                             ph[2 * kc + 1][0], ph[2 * kc + 1][1]};
#pragma unroll
            for (int dn = 0; dn < 4; dn++) {
                uint32_t r0, r1, r2, r3;
                ldsm_x4_t(vbase + vb_rel[dn] + kc * 16 * KSTR * 2, r0, r1, r2, r3);
                uint32_t bb[2];
                bb[0] = r0; bb[1] = r1;
                mma_f16(accO[2 * dn], a, bb);
                bb[0] = r2; bb[1] = r3;
                mma_f16(accO[2 * dn + 1], a, bb);
            }
        }
        __syncthreads();
    }

    // epilogue: O / l -> fp16, into proj GEMM A input g_of[token][h*64+d]
    float i0 = 1.0f / l_lo, i1 = 1.0f / l_hi;
    int qn = qt * 64 + w * 16 + (lane >> 2);
    int col0 = h * 64 + c2;
#pragma unroll
    for (int j = 0; j < 8; j++) {
        size_t off0 = (size_t)(b * 2048 + qn) * 1024 + col0 + 8 * j;
        size_t off1 = (size_t)(b * 2048 + qn + 8) * 1024 + col0 + 8 * j;
        *(__half2*)(g_of + off0) = __floats2half2_rn(accO[j][0] * i0,
                                                     accO[j][1] * i0);
        *(__half2*)(g_of + off1) = __floats2half2_rn(accO[j][2] * i1,
                                                     accO[j][3] * i1);
    }
}

// ---------------------------------------------------------------------------
extern "C" void kernel_launch(void* const* d_in, const int* in_sizes, int n_in,
                              void* d_out, int out_size) {
    const float* x      = (const float*)d_in[0];
    const float* mWin   = (const float*)d_in[1];
    const float* w_qkv  = (const float*)d_in[2];
    const float* w_proj = (const float*)d_in[3];
    const float* b_proj = (const float*)d_in[4];
    float* out = (float*)d_out;

    __half *xh, *wqh, *wql, *wph, *wpl, *of;
    cudaGetSymbolAddress((void**)&xh,  g_xh);
    cudaGetSymbolAddress((void**)&wqh, g_wqh);
    cudaGetSymbolAddress((void**)&wql, g_wql);
    cudaGetSymbolAddress((void**)&wph, g_wph);
    cudaGetSymbolAddress((void**)&wpl, g_wpl);
    cudaGetSymbolAddress((void**)&of,  g_of);

    cudaFuncSetAttribute(gemm_mma, cudaFuncAttributeMaxDynamicSharedMemorySize,
                         GEMM_SMEM_BYTES);
    cudaFuncSetAttribute(attn_mma, cudaFuncAttributeMaxDynamicSharedMemorySize,
                         ATTN_SMEM_BYTES);

    // Conversions
    tofp16_kernel<<<8192, 256>>>(x, xh);
    splitf16_kernel<<<3072, 256>>>(w_qkv, wqh, wql);
    splitf16_kernel<<<1024, 256>>>(w_proj, wph, wpl);

    // QKV projection (fp16 2-pass) -> Qs (scaled), K, V
    gemm_mma<<<dim3(24, 64), 256, GEMM_SMEM_BYTES>>>(xh, wqh, wql,
                                                     nullptr, nullptr, 0);

    // Flash attention (mma.sync fp16), writes g_of
    attn_mma<<<2048, 128, ATTN_SMEM_BYTES>>>(mWin);

    // Output projection (fp16 2-pass) + bias
    gemm_mma<<<dim3(8, 64), 256, GEMM_SMEM_BYTES>>>(of, wph, wpl,
                                                    b_proj, out, 1);
}

// round 12
// speedup vs baseline: 1.7430x; 1.1647x over previous
#include <cuda_runtime.h>
#include <cuda_fp16.h>
#include <cstdint>

// Problem constants
#define BATCH 4
#define SEQ   2048
#define CH    1024
#define HEADS 16
#define HD    64
#define QSCALE 0.18033688011112042f   // 0.125 * log2(e)
#define LOG2E  1.4426950408889634f

// ---------------------------------------------------------------------------
// Scratch (allocation-free: __device__ globals)
// ---------------------------------------------------------------------------
__device__ __align__(16) __half g_qh[BATCH * HEADS * SEQ * HD];  // Q*QSCALE fp16
__device__ __align__(16) __half g_kf[BATCH * HEADS * SEQ * HD];
__device__ __align__(16) __half g_vf[BATCH * HEADS * SEQ * HD];
__device__ __align__(16) __half g_of[8192 * 1024];               // attn output

__device__ __align__(16) __half g_xh [8192 * 1024];
__device__ __align__(16) __half g_wqh[3072 * 1024];
__device__ __align__(16) __half g_wph[1024 * 1024];
__device__ __align__(16) __half g_wpl[1024 * 1024];

// ---------------------------------------------------------------------------
// Warp-MMA helpers (portable sm_80+ path; tcgen05 rejected by sm_100 target)
// ---------------------------------------------------------------------------
__device__ __forceinline__ uint32_t smem_u32(const void* p) {
    uint32_t a;
    asm("{ .reg .u64 t; cvta.to.shared.u64 t, %1; cvt.u32.u64 %0, t; }"
        : "=r"(a) : "l"(p));
    return a;
}

__device__ __forceinline__ void ldsm_x4(uint32_t addr, uint32_t& r0, uint32_t& r1,
                                        uint32_t& r2, uint32_t& r3) {
    asm volatile("ldmatrix.sync.aligned.m8n8.x4.shared.b16 {%0,%1,%2,%3}, [%4];"
                 : "=r"(r0), "=r"(r1), "=r"(r2), "=r"(r3) : "r"(addr));
}

__device__ __forceinline__ void ldsm_x4_t(uint32_t addr, uint32_t& r0, uint32_t& r1,
                                          uint32_t& r2, uint32_t& r3) {
    asm volatile("ldmatrix.sync.aligned.m8n8.x4.trans.shared.b16 {%0,%1,%2,%3}, [%4];"
                 : "=r"(r0), "=r"(r1), "=r"(r2), "=r"(r3) : "r"(addr));
}

__device__ __forceinline__ void mma_f16(float* d, const uint32_t* a,
                                        const uint32_t* b) {
    asm volatile(
        "mma.sync.aligned.m16n8k16.row.col.f32.f16.f16.f32 "
        "{%0,%1,%2,%3}, {%4,%5,%6,%7}, {%8,%9}, {%0,%1,%2,%3};"
        : "+f"(d[0]), "+f"(d[1]), "+f"(d[2]), "+f"(d[3])
        : "r"(a[0]), "r"(a[1]), "r"(a[2]), "r"(a[3]), "r"(b[0]), "r"(b[1]));
}

__device__ __forceinline__ void cp16(uint32_t dst, const void* src) {
    asm volatile("cp.async.cg.shared.global [%0], [%1], 16;"
                 :: "r"(dst), "l"(src));
}

__device__ __forceinline__ uint32_t pack_h2(float a, float b) {
    __half2 h = __floats2half2_rn(a, b);
    return *reinterpret_cast<uint32_t*>(&h);
}

// exp2 on FMA pipe: magic-number round + degree-5 Taylor. x <= 0 expected.
__device__ __forceinline__ float exp2_poly(float x) {
    x = fmaxf(x, -126.0f);
    float z = x + 12582912.0f;            // 1.5*2^23: RN rounds x to integer
    float r = z - 12582912.0f;            // r = rint(x)
    float f = x - r;                      // f in [-0.5, 0.5]
    float p = 1.3333558146e-3f;
    p = fmaf(p, f, 9.6181291076e-3f);
    p = fmaf(p, f, 5.5504108665e-2f);
    p = fmaf(p, f, 2.4022650696e-1f);
    p = fmaf(p, f, 6.9314718056e-1f);
    p = fmaf(p, f, 1.0f);
    int e = __float_as_int(z) - 0x4B400000;     // integer r from magic mantissa
    return p * __int_as_float((e + 127) << 23);
}

// ---------------------------------------------------------------------------
// Conversions: fp32 -> fp16, and fp32 -> (fp16 hi, fp16 lo) split.
// ---------------------------------------------------------------------------
__global__ __launch_bounds__(256) void tofp16_kernel(const float* __restrict__ src,
                                                     __half* __restrict__ dst) {
    int i = blockIdx.x * 256 + threadIdx.x;
    float4 v = ((const float4*)src)[i];
    ((__half2*)dst)[2 * i]     = __floats2half2_rn(v.x, v.y);
    ((__half2*)dst)[2 * i + 1] = __floats2half2_rn(v.z, v.w);
}

__global__ __launch_bounds__(256) void splitf16_kernel(const float* __restrict__ src,
                                                       __half* __restrict__ hi,
                                                       __half* __restrict__ lo) {
    int i = blockIdx.x * 256 + threadIdx.x;
    float4 v = ((const float4*)src)[i];
    __half2 h0 = __floats2half2_rn(v.x, v.y);
    __half2 h1 = __floats2half2_rn(v.z, v.w);
    __half2 l0 = __floats2half2_rn(v.x - __low2float(h0), v.y - __high2float(h0));
    __half2 l1 = __floats2half2_rn(v.z - __low2float(h1), v.w - __high2float(h1));
    ((__half2*)hi)[2 * i]     = h0;
    ((__half2*)hi)[2 * i + 1] = h1;
    ((__half2*)lo)[2 * i]     = l0;
    ((__half2*)lo)[2 * i + 1] = l1;
}

// ---------------------------------------------------------------------------
// mma.sync GEMM: D = A * (Bh [+ Bl])^T, fp16. Bl == nullptr -> single pass.
// Block 128x128, 8 warps (2x4), warp tile 64x32, K chunk 32, 32 chunks,
// 2-stage cp.async pipeline. Stage = A + Bh + Bl = 30,720 B; 2 stages.
// mode 0: qkv -> write fp16 Qs (scaled), K, V.  mode 1: out = D + bias.
// ---------------------------------------------------------------------------
#define LDSG 40
#define MATB 10240                   // one 128x40 fp16 matrix, bytes
#define STGB 30720                   // stage bytes (A+Bh+Bl slots)
#define GEMM_SMEM_BYTES 61440

__global__ __launch_bounds__(256) void gemm_mma(
    const __half* __restrict__ A, const __half* __restrict__ Bh,
    const __half* __restrict__ Bl,
    const float* __restrict__ bias, float* __restrict__ out, int mode) {
    extern __shared__ __align__(16) __half smp[];

    const int tid = threadIdx.x;
    const int wid = tid >> 5, lane = tid & 31;
    const int m0 = blockIdx.y * 128;
    const int n0 = blockIdx.x * 128;
    const int wm = (wid >> 2) * 64;
    const int wn = (wid & 3) * 32;

    float acc[4][4][4] = {};

    const uint32_t sb = smem_u32(smp);

    // cp.async staging: thread -> (row, 32B half-row chunk)
    const int srow = tid >> 1;
    const int sco  = (tid & 1) * 16;               // halves
    const uint32_t sdst = (srow * LDSG + sco) * 2;

    auto stage = [&](int cn, int buf) {
        int k0 = cn * 32;
        uint32_t ab = sb + buf * STGB + sdst;
        const __half* as = A  + (size_t)(m0 + srow) * 1024 + k0 + sco;
        const __half* bh = Bh + (size_t)(n0 + srow) * 1024 + k0 + sco;
        cp16(ab, as);               cp16(ab + 16, as + 8);
        cp16(ab + MATB, bh);        cp16(ab + MATB + 16, bh + 8);
        if (Bl) {
            const __half* bl = Bl + (size_t)(n0 + srow) * 1024 + k0 + sco;
            cp16(ab + 2 * MATB, bl);
            cp16(ab + 2 * MATB + 16, bl + 8);
        }
    };

    // ldmatrix relative offsets within a stage
    uint32_t a_rel[4], bh_rel[2];
#pragma unroll
    for (int i = 0; i < 4; i++)
        a_rel[i] = ((wm + i * 16 + (lane & 15)) * LDSG + ((lane >> 4) << 3)) * 2;
#pragma unroll
    for (int p = 0; p < 2; p++)
        bh_rel[p] = MATB +
            ((wn + p * 16 + ((lane >> 4) << 3) + (lane & 7)) * LDSG +
             (((lane >> 3) & 1) << 3)) * 2;

    stage(0, 0);
    asm volatile("cp.async.commit_group;" ::: "memory");

    for (int c = 0; c < 32; c++) {
        if (c + 1 < 32) {
            stage(c + 1, (c + 1) & 1);
            asm volatile("cp.async.commit_group;" ::: "memory");
            asm volatile("cp.async.wait_group 1;" ::: "memory");
        } else {
            asm volatile("cp.async.wait_group 0;" ::: "memory");
        }
        __syncthreads();

        const uint32_t soff = sb + (c & 1) * STGB;
#pragma unroll
        for (int kk = 0; kk < 2; kk++) {
            uint32_t a[4][4], b[2][4];
#pragma unroll
            for (int i = 0; i < 4; i++)
                ldsm_x4(soff + a_rel[i] + kk * 32, a[i][0], a[i][1], a[i][2], a[i][3]);
            // pass 1: Bh
#pragma unroll
            for (int p = 0; p < 2; p++)
                ldsm_x4(soff + bh_rel[p] + kk * 32, b[p][0], b[p][1], b[p][2], b[p][3]);
#pragma unroll
            for (int i = 0; i < 4; i++)
#pragma unroll
                for (int j = 0; j < 4; j++)
                    mma_f16(acc[i][j], a[i], &b[j >> 1][(j & 1) * 2]);
            // pass 2: Bl (same A), only when provided
            if (Bl) {
#pragma unroll
                for (int p = 0; p < 2; p++)
                    ldsm_x4(soff + bh_rel[p] + MATB + kk * 32,
                            b[p][0], b[p][1], b[p][2], b[p][3]);
#pragma unroll
                for (int i = 0; i < 4; i++)
#pragma unroll
                    for (int j = 0; j < 4; j++)
                        mma_f16(acc[i][j], a[i], &b[j >> 1][(j & 1) * 2]);
            }
        }
        __syncthreads();
    }

    const int rl = lane >> 2;
    const int cl = (lane & 3) * 2;
#pragma unroll
    for (int i = 0; i < 4; i++) {
#pragma unroll
        for (int j = 0; j < 4; j++) {
#pragma unroll
            for (int pr = 0; pr < 2; pr++) {
                int r  = m0 + wm + i * 16 + rl + pr * 8;
                int cg = n0 + wn + j * 8 + cl;
                float2 v = make_float2(acc[i][j][pr * 2], acc[i][j][pr * 2 + 1]);
                if (mode == 0) {
                    int three = cg >> 10;
                    int h = (cg >> 6) & 15;
                    int hd = cg & 63;
                    int b_ = r >> 11, nn = r & 2047;
                    size_t off = (size_t)((b_ * 16 + h) * 2048 + nn) * 64 + hd;
                    if (three == 0) {
                        *(__half2*)(g_qh + off) =
                            __floats2half2_rn(v.x * QSCALE, v.y * QSCALE);
                    } else if (three == 1) {
                        *(__half2*)(g_kf + off) = __floats2half2_rn(v.x, v.y);
                    } else {
                        *(__half2*)(g_vf + off) = __floats2half2_rn(v.x, v.y);
                    }
                } else {
                    v.x += bias[cg];
                    v.y += bias[cg + 1];
                    *(float2*)(out + (size_t)r * 1024 + cg) = v;
                }
            }
        }
    }
}

// ---------------------------------------------------------------------------
// mma.sync flash attention. Block = (bh, 64-query tile), 4 warps (16 rows each).
// S = Q*K fp16 (1 pass), softmax in log2 domain (FMA-pipe exp2),
// O += P(fp16)*V(fp16). K/V double-buffered via cp.async.
// Epilogue writes O as single fp16 (proj GEMM A input).
// smem: Qs[64][72] | bias[64] | {K[64][72],V[64][72]} x2  = 46,336 B dynamic.
// ---------------------------------------------------------------------------
#define QSTR 72
#define KSTR 72
#define SM_KV0 9472
#define KVBUF  18432
#define ATTN_SMEM_BYTES 46336

__device__ __forceinline__ void stage_kv(uint32_t kd, const __half* ksrc,
                                         const __half* vsrc, int tid) {
#pragma unroll
    for (int t = 0; t < 4; t++) {
        int idx = tid + 128 * t;
        int r = idx >> 3, u = idx & 7;
        cp16(kd + (r * KSTR + u * 8) * 2, ksrc + r * 64 + u * 8);
        cp16(kd + 9216 + (r * KSTR + u * 8) * 2, vsrc + r * 64 + u * 8);
    }
}

__global__ __launch_bounds__(128) void attn_mma(const float* __restrict__ mWin) {
    extern __shared__ char smem[];
    float* bias_s = (float*)(smem + 9216);

    const int tid = threadIdx.x;
    const int lane = tid & 31, w = tid >> 5;
    const int qt = blockIdx.x & 31;
    const int bh = blockIdx.x >> 5;
    const int b = bh >> 4, h = bh & 15;

    const __half* qh_g = g_qh + ((size_t)bh * 2048 + qt * 64) * 64;
    const __half* kf_g = g_kf + (size_t)bh * 2048 * 64;
    const __half* vf_g = g_vf + (size_t)bh * 2048 * 64;

    const uint32_t sbase = smem_u32(smem);

    // issue cp.async for key tile 0
    stage_kv(sbase + SM_KV0, kf_g, vf_g, tid);
    asm volatile("cp.async.commit_group;" ::: "memory");

    // stage Q (64 rows x 64 halves, stride 72)
#pragma unroll
    for (int t = 0; t < 4; t++) {
        int idx = tid + 128 * t;
        int r = idx >> 3, u = idx & 7;
        *(uint4*)(smem + ((size_t)r * QSTR + u * 8) * 2) =
            *(const uint4*)(qh_g + r * 64 + u * 8);
    }
    __syncthreads();

    // preload Q fragments (4 k-chunks x 4 regs)
    uint32_t aQ[4][4];
#pragma unroll
    for (int kc = 0; kc < 4; kc++) {
        uint32_t addr = sbase +
            ((w * 16 + (lane & 15)) * QSTR + kc * 16 + (lane >> 4) * 8) * 2;
        ldsm_x4(addr, aQ[kc][0], aQ[kc][1], aQ[kc][2], aQ[kc][3]);
    }

    // ldmatrix relative offsets
    uint32_t kb_rel[4], vb_rel[4];
#pragma unroll
    for (int p = 0; p < 4; p++)
        kb_rel[p] = ((p * 16 + ((lane >> 4) << 3) + (lane & 7)) * KSTR +
                     (((lane >> 3) & 1) << 3)) * 2;
#pragma unroll
    for (int dn = 0; dn < 4; dn++)
        vb_rel[dn] = ((((lane >> 3) & 1) * 8 + (lane & 7)) * KSTR +
                      dn * 16 + (lane >> 4) * 8) * 2;

    float accO[8][4] = {};
    float m_lo = -1e30f, m_hi = -1e30f, l_lo = 0.0f, l_hi = 0.0f;
    const int c2 = (lane & 3) * 2;

    for (int kt = 0; kt < 32; kt++) {
        const int buf = kt & 1;
        if (kt + 1 < 32) {
            stage_kv(sbase + SM_KV0 + (buf ^ 1) * KVBUF,
                     kf_g + (size_t)(kt + 1) * 64 * 64,
                     vf_g + (size_t)(kt + 1) * 64 * 64, tid);
            asm volatile("cp.async.commit_group;" ::: "memory");
            asm volatile("cp.async.wait_group 1;" ::: "memory");
        } else {
            asm volatile("cp.async.wait_group 0;" ::: "memory");
        }
        if (tid < 64)
            bias_s[tid] = (mWin[b * 2048 + kt * 64 + tid] * 100.0f - 100.0f) * LOG2E;
        __syncthreads();

        const uint32_t kbase = sbase + SM_KV0 + buf * KVBUF;
        const uint32_t vbase = kbase + 9216;

        // S = Q*K (single fp16 pass)
        float accS[8][4] = {};
#pragma unroll
        for (int dc = 0; dc < 4; dc++) {
#pragma unroll
            for (int p = 0; p < 4; p++) {
                uint32_t b0, b1, b2, b3;
                ldsm_x4(kbase + kb_rel[p] + dc * 32, b0, b1, b2, b3);
                uint32_t bb[2];
                bb[0] = b0; bb[1] = b1;
                mma_f16(accS[2 * p], aQ[dc], bb);
                bb[0] = b2; bb[1] = b3;
                mma_f16(accS[2 * p + 1], aQ[dc], bb);
            }
        }

        // + key bias (log2 units)
#pragma unroll
        for (int j = 0; j < 8; j++) {
            float b0v = bias_s[8 * j + c2], b1v = bias_s[8 * j + c2 + 1];
            accS[j][0] += b0v; accS[j][1] += b1v;
            accS[j][2] += b0v; accS[j][3] += b1v;
        }

        // online softmax (rows r=lane>>2 and r+8)
        float mx0 = -1e30f, mx1 = -1e30f;
#pragma unroll
        for (int j = 0; j < 8; j++) {
            mx0 = fmaxf(mx0, fmaxf(accS[j][0], accS[j][1]));
            mx1 = fmaxf(mx1, fmaxf(accS[j][2], accS[j][3]));
        }
        mx0 = fmaxf(mx0, __shfl_xor_sync(0xffffffffu, mx0, 1));
        mx0 = fmaxf(mx0, __shfl_xor_sync(0xffffffffu, mx0, 2));
        mx1 = fmaxf(mx1, __shfl_xor_sync(0xffffffffu, mx1, 1));
        mx1 = fmaxf(mx1, __shfl_xor_sync(0xffffffffu, mx1, 2));
        float mn0 = fmaxf(m_lo, mx0), mn1 = fmaxf(m_hi, mx1);
        float cor0 = exp2_poly(m_lo - mn0), cor1 = exp2_poly(m_hi - mn1);
        m_lo = mn0; m_hi = mn1;

        float s0 = 0.0f, s1 = 0.0f;
#pragma unroll
        for (int j = 0; j < 8; j++) {
            accS[j][0] = exp2_poly(accS[j][0] - m_lo);
            accS[j][1] = exp2_poly(accS[j][1] - m_lo);
            accS[j][2] = exp2_poly(accS[j][2] - m_hi);
            accS[j][3] = exp2_poly(accS[j][3] - m_hi);
            s0 += accS[j][0] + accS[j][1];
            s1 += accS[j][2] + accS[j][3];
        }
        s0 += __shfl_xor_sync(0xffffffffu, s0, 1);
        s0 += __shfl_xor_sync(0xffffffffu, s0, 2);
        s1 += __shfl_xor_sync(0xffffffffu, s1, 1);
        s1 += __shfl_xor_sync(0xffffffffu, s1, 2);
        l_lo = l_lo * cor0 + s0;
        l_hi = l_hi * cor1 + s1;
#pragma unroll
        for (int j = 0; j < 8; j++) {
            accO[j][0] *= cor0; accO[j][1] *= cor0;
            accO[j][2] *= cor1; accO[j][3] *= cor1;
        }

        // pack P -> fp16 A-fragments (in registers)
        uint32_t ph[8][2];
#pragma unroll
        for (int j = 0; j < 8; j++) {
            ph[j][0] = pack_h2(accS[j][0], accS[j][1]);
            ph[j][1] = pack_h2(accS[j][2], accS[j][3]);
        }

        // O += P * V  (V via ldmatrix.trans)
#pragma unroll
        for (int kc = 0; kc < 4; kc++) {
            uint32_t a[4] = {ph[2 * kc][0], ph[2 * kc][1],
                             ph[2 * kc + 1][0], ph[2 * kc + 1][1]};
#pragma unroll
            for (int dn = 0; dn < 4; dn++) {
                uint32_t r0, r1, r2, r3;
                ldsm_x4_t(vbase + vb_rel[dn] + kc * 16 * KSTR * 2, r0, r1, r2, r3);
                uint32_t bb[2];
                bb[0] = r0; bb[1] = r1;
                mma_f16(accO[2 * dn], a, bb);
                bb[0] = r2; bb[1] = r3;
                mma_f16(accO[2 * dn + 1], a, bb);
            }
        }
        __syncthreads();
    }

    // epilogue: O / l -> fp16, into proj GEMM A input g_of[token][h*64+d]
    float i0 = 1.0f / l_lo, i1 = 1.0f / l_hi;
    int qn = qt * 64 + w * 16 + (lane >> 2);
    int col0 = h * 64 + c2;
#pragma unroll
    for (int j = 0; j < 8; j++) {
        size_t off0 = (size_t)(b * 2048 + qn) * 1024 + col0 + 8 * j;
        size_t off1 = (size_t)(b * 2048 + qn + 8) * 1024 + col0 + 8 * j;
        *(__half2*)(g_of + off0) = __floats2half2_rn(accO[j][0] * i0,
                                                     accO[j][1] * i0);
        *(__half2*)(g_of + off1) = __floats2half2_rn(accO[j][2] * i1,
                                                     accO[j][3] * i1);
    }
}

// ---------------------------------------------------------------------------
extern "C" void kernel_launch(void* const* d_in, const int* in_sizes, int n_in,
                              void* d_out, int out_size) {
    const float* x      = (const float*)d_in[0];
    const float* mWin   = (const float*)d_in[1];
    const float* w_qkv  = (const float*)d_in[2];
    const float* w_proj = (const float*)d_in[3];
    const float* b_proj = (const float*)d_in[4];
    float* out = (float*)d_out;

    __half *xh, *wqh, *wph, *wpl, *of;
    cudaGetSymbolAddress((void**)&xh,  g_xh);
    cudaGetSymbolAddress((void**)&wqh, g_wqh);
    cudaGetSymbolAddress((void**)&wph, g_wph);
    cudaGetSymbolAddress((void**)&wpl, g_wpl);
    cudaGetSymbolAddress((void**)&of,  g_of);

    cudaFuncSetAttribute(gemm_mma, cudaFuncAttributeMaxDynamicSharedMemorySize,
                         GEMM_SMEM_BYTES);
    cudaFuncSetAttribute(attn_mma, cudaFuncAttributeMaxDynamicSharedMemorySize,
                         ATTN_SMEM_BYTES);

    // Conversions
    tofp16_kernel<<<8192, 256>>>(x, xh);
    tofp16_kernel<<<3072, 256>>>(w_qkv, wqh);
    splitf16_kernel<<<1024, 256>>>(w_proj, wph, wpl);

    // QKV projection (fp16 SINGLE pass — outputs are fp16-rounded anyway)
    gemm_mma<<<dim3(24, 64), 256, GEMM_SMEM_BYTES>>>(xh, wqh, nullptr,
                                                     nullptr, nullptr, 0);

    // Flash attention (mma.sync fp16), writes g_of
    attn_mma<<<2048, 128, ATTN_SMEM_BYTES>>>(mWin);

    // Output projection (fp16 2-pass: final fp32 output, keep the Wl term)
    gemm_mma<<<dim3(8, 64), 256, GEMM_SMEM_BYTES>>>(of, wph, wpl,
                                                    b_proj, out, 1);
}

// round 13
// speedup vs baseline: 1.7432x; 1.0001x over previous
#include <cuda_runtime.h>
#include <cuda_fp16.h>
#include <cstdint>

// Problem constants
#define BATCH 4
#define SEQ   2048
#define CH    1024
#define HEADS 16
#define HD    64
#define QSCALE 0.18033688011112042f   // 0.125 * log2(e)
#define LOG2E  1.4426950408889634f

// ---------------------------------------------------------------------------
// Scratch (allocation-free: __device__ globals)
// ---------------------------------------------------------------------------
__device__ __align__(16) __half g_qh[BATCH * HEADS * SEQ * HD];  // Q*QSCALE fp16
__device__ __align__(16) __half g_kf[BATCH * HEADS * SEQ * HD];
__device__ __align__(16) __half g_vf[BATCH * HEADS * SEQ * HD];
__device__ __align__(16) __half g_of[8192 * 1024];               // attn output

__device__ __align__(16) __half g_xh [8192 * 1024];
__device__ __align__(16) __half g_wqh[3072 * 1024];
__device__ __align__(16) __half g_wph[1024 * 1024];
__device__ __align__(16) __half g_wpl[1024 * 1024];

// ---------------------------------------------------------------------------
// Warp-MMA helpers (portable sm_80+ path; tcgen05 rejected by sm_100 target)
// ---------------------------------------------------------------------------
__device__ __forceinline__ uint32_t smem_u32(const void* p) {
    uint32_t a;
    asm("{ .reg .u64 t; cvta.to.shared.u64 t, %1; cvt.u32.u64 %0, t; }"
        : "=r"(a) : "l"(p));
    return a;
}

__device__ __forceinline__ void ldsm_x4(uint32_t addr, uint32_t& r0, uint32_t& r1,
                                        uint32_t& r2, uint32_t& r3) {
    asm volatile("ldmatrix.sync.aligned.m8n8.x4.shared.b16 {%0,%1,%2,%3}, [%4];"
                 : "=r"(r0), "=r"(r1), "=r"(r2), "=r"(r3) : "r"(addr));
}

__device__ __forceinline__ void ldsm_x4_t(uint32_t addr, uint32_t& r0, uint32_t& r1,
                                          uint32_t& r2, uint32_t& r3) {
    asm volatile("ldmatrix.sync.aligned.m8n8.x4.trans.shared.b16 {%0,%1,%2,%3}, [%4];"
                 : "=r"(r0), "=r"(r1), "=r"(r2), "=r"(r3) : "r"(addr));
}

__device__ __forceinline__ void mma_f16(float* d, const uint32_t* a,
                                        const uint32_t* b) {
    asm volatile(
        "mma.sync.aligned.m16n8k16.row.col.f32.f16.f16.f32 "
        "{%0,%1,%2,%3}, {%4,%5,%6,%7}, {%8,%9}, {%0,%1,%2,%3};"
        : "+f"(d[0]), "+f"(d[1]), "+f"(d[2]), "+f"(d[3])
        : "r"(a[0]), "r"(a[1]), "r"(a[2]), "r"(a[3]), "r"(b[0]), "r"(b[1]));
}

__device__ __forceinline__ void cp16(uint32_t dst, const void* src) {
    asm volatile("cp.async.cg.shared.global [%0], [%1], 16;"
                 :: "r"(dst), "l"(src));
}

__device__ __forceinline__ uint32_t pack_h2(float a, float b) {
    __half2 h = __floats2half2_rn(a, b);
    return *reinterpret_cast<uint32_t*>(&h);
}

// exp2 on FMA pipe: magic-number round + degree-5 Taylor. x <= 0 expected.
__device__ __forceinline__ float exp2_poly(float x) {
    x = fmaxf(x, -126.0f);
    float z = x + 12582912.0f;            // 1.5*2^23: RN rounds x to integer
    float r = z - 12582912.0f;            // r = rint(x)
    float f = x - r;                      // f in [-0.5, 0.5]
    float p = 1.3333558146e-3f;
    p = fmaf(p, f, 9.6181291076e-3f);
    p = fmaf(p, f, 5.5504108665e-2f);
    p = fmaf(p, f, 2.4022650696e-1f);
    p = fmaf(p, f, 6.9314718056e-1f);
    p = fmaf(p, f, 1.0f);
    int e = __float_as_int(z) - 0x4B400000;     // integer r from magic mantissa
    return p * __int_as_float((e + 127) << 23);
}

// ---------------------------------------------------------------------------
// Conversions: fp32 -> fp16, and fp32 -> (fp16 hi, fp16 lo) split.
// ---------------------------------------------------------------------------
__global__ __launch_bounds__(256) void tofp16_kernel(const float* __restrict__ src,
                                                     __half* __restrict__ dst) {
    int i = blockIdx.x * 256 + threadIdx.x;
    float4 v = ((const float4*)src)[i];
    ((__half2*)dst)[2 * i]     = __floats2half2_rn(v.x, v.y);
    ((__half2*)dst)[2 * i + 1] = __floats2half2_rn(v.z, v.w);
}

__global__ __launch_bounds__(256) void splitf16_kernel(const float* __restrict__ src,
                                                       __half* __restrict__ hi,
                                                       __half* __restrict__ lo) {
    int i = blockIdx.x * 256 + threadIdx.x;
    float4 v = ((const float4*)src)[i];
    __half2 h0 = __floats2half2_rn(v.x, v.y);
    __half2 h1 = __floats2half2_rn(v.z, v.w);
    __half2 l0 = __floats2half2_rn(v.x - __low2float(h0), v.y - __high2float(h0));
    __half2 l1 = __floats2half2_rn(v.z - __low2float(h1), v.w - __high2float(h1));
    ((__half2*)hi)[2 * i]     = h0;
    ((__half2*)hi)[2 * i + 1] = h1;
    ((__half2*)lo)[2 * i]     = l0;
    ((__half2*)lo)[2 * i + 1] = l1;
}

// ---------------------------------------------------------------------------
// mma.sync GEMM: D = A * (Bh [+ Bl])^T, fp16. Bl == nullptr -> single pass.
// Block 128x128, 8 warps (2x4), warp tile 64x32, K chunk 32, 32 chunks,
// 2-stage cp.async pipeline. Stage = A + Bh + Bl = 30,720 B; 2 stages.
// mode 0: qkv -> write fp16 Qs (scaled), K, V.  mode 1: out = D + bias.
// ---------------------------------------------------------------------------
#define LDSG 40
#define MATB 10240                   // one 128x40 fp16 matrix, bytes
#define STGB 30720                   // stage bytes (A+Bh+Bl slots)
#define GEMM_SMEM_BYTES 61440

__global__ __launch_bounds__(256) void gemm_mma(
    const __half* __restrict__ A, const __half* __restrict__ Bh,
    const __half* __restrict__ Bl,
    const float* __restrict__ bias, float* __restrict__ out, int mode) {
    extern __shared__ __align__(16) __half smp[];

    const int tid = threadIdx.x;
    const int wid = tid >> 5, lane = tid & 31;
    const int m0 = blockIdx.y * 128;
    const int n0 = blockIdx.x * 128;
    const int wm = (wid >> 2) * 64;
    const int wn = (wid & 3) * 32;

    float acc[4][4][4] = {};

    const uint32_t sb = smem_u32(smp);

    // cp.async staging: thread -> (row, 32B half-row chunk)
    const int srow = tid >> 1;
    const int sco  = (tid & 1) * 16;               // halves
    const uint32_t sdst = (srow * LDSG + sco) * 2;

    auto stage = [&](int cn, int buf) {
        int k0 = cn * 32;
        uint32_t ab = sb + buf * STGB + sdst;
        const __half* as = A  + (size_t)(m0 + srow) * 1024 + k0 + sco;
        const __half* bh = Bh + (size_t)(n0 + srow) * 1024 + k0 + sco;
        cp16(ab, as);               cp16(ab + 16, as + 8);
        cp16(ab + MATB, bh);        cp16(ab + MATB + 16, bh + 8);
        if (Bl) {
            const __half* bl = Bl + (size_t)(n0 + srow) * 1024 + k0 + sco;
            cp16(ab + 2 * MATB, bl);
            cp16(ab + 2 * MATB + 16, bl + 8);
        }
    };

    // ldmatrix relative offsets within a stage
    uint32_t a_rel[4], bh_rel[2];
#pragma unroll
    for (int i = 0; i < 4; i++)
        a_rel[i] = ((wm + i * 16 + (lane & 15)) * LDSG + ((lane >> 4) << 3)) * 2;
#pragma unroll
    for (int p = 0; p < 2; p++)
        bh_rel[p] = MATB +
            ((wn + p * 16 + ((lane >> 4) << 3) + (lane & 7)) * LDSG +
             (((lane >> 3) & 1) << 3)) * 2;

    stage(0, 0);
    asm volatile("cp.async.commit_group;" ::: "memory");

    for (int c = 0; c < 32; c++) {
        if (c + 1 < 32) {
            stage(c + 1, (c + 1) & 1);
            asm volatile("cp.async.commit_group;" ::: "memory");
            asm volatile("cp.async.wait_group 1;" ::: "memory");
        } else {
            asm volatile("cp.async.wait_group 0;" ::: "memory");
        }
        __syncthreads();

        const uint32_t soff = sb + (c & 1) * STGB;
#pragma unroll
        for (int kk = 0; kk < 2; kk++) {
            uint32_t a[4][4], b[2][4];
#pragma unroll
            for (int i = 0; i < 4; i++)
                ldsm_x4(soff + a_rel[i] + kk * 32, a[i][0], a[i][1], a[i][2], a[i][3]);
            // pass 1: Bh
#pragma unroll
            for (int p = 0; p < 2; p++)
                ldsm_x4(soff + bh_rel[p] + kk * 32, b[p][0], b[p][1], b[p][2], b[p][3]);
#pragma unroll
            for (int i = 0; i < 4; i++)
#pragma unroll
                for (int j = 0; j < 4; j++)
                    mma_f16(acc[i][j], a[i], &b[j >> 1][(j & 1) * 2]);
            // pass 2: Bl (same A), only when provided
            if (Bl) {
#pragma unroll
                for (int p = 0; p < 2; p++)
                    ldsm_x4(soff + bh_rel[p] + MATB + kk * 32,
                            b[p][0], b[p][1], b[p][2], b[p][3]);
#pragma unroll
                for (int i = 0; i < 4; i++)
#pragma unroll
                    for (int j = 0; j < 4; j++)
                        mma_f16(acc[i][j], a[i], &b[j >> 1][(j & 1) * 2]);
            }
        }
        __syncthreads();
    }

    const int rl = lane >> 2;
    const int cl = (lane & 3) * 2;
#pragma unroll
    for (int i = 0; i < 4; i++) {
#pragma unroll
        for (int j = 0; j < 4; j++) {
#pragma unroll
            for (int pr = 0; pr < 2; pr++) {
                int r  = m0 + wm + i * 16 + rl + pr * 8;
                int cg = n0 + wn + j * 8 + cl;
                float2 v = make_float2(acc[i][j][pr * 2], acc[i][j][pr * 2 + 1]);
                if (mode == 0) {
                    int three = cg >> 10;
                    int h = (cg >> 6) & 15;
                    int hd = cg & 63;
                    int b_ = r >> 11, nn = r & 2047;
                    size_t off = (size_t)((b_ * 16 + h) * 2048 + nn) * 64 + hd;
                    if (three == 0) {
                        *(__half2*)(g_qh + off) =
                            __floats2half2_rn(v.x * QSCALE, v.y * QSCALE);
                    } else if (three == 1) {
                        *(__half2*)(g_kf + off) = __floats2half2_rn(v.x, v.y);
                    } else {
                        *(__half2*)(g_vf + off) = __floats2half2_rn(v.x, v.y);
                    }
                } else {
                    v.x += bias[cg];
                    v.y += bias[cg + 1];
                    *(float2*)(out + (size_t)r * 1024 + cg) = v;
                }
            }
        }
    }
}

// ---------------------------------------------------------------------------
// mma.sync flash attention. Block = (bh, 64-query tile), 4 warps (16 rows each).
// S = Q*K fp16 (1 pass), softmax in log2 domain (FMA-pipe exp2),
// O += P(fp16)*V(fp16). K/V double-buffered via cp.async.
// Epilogue writes O as single fp16 (proj GEMM A input).
// smem: Qs[64][72] | bias[64] | {K[64][72],V[64][72]} x2  = 46,336 B dynamic.
// ---------------------------------------------------------------------------
#define QSTR 72
#define KSTR 72
#define SM_KV0 9472
#define KVBUF  18432
#define ATTN_SMEM_BYTES 46336

__device__ __forceinline__ void stage_kv(uint32_t kd, const __half* ksrc,
                                         const __half* vsrc, int tid) {
#pragma unroll
    for (int t = 0; t < 4; t++) {
        int idx = tid + 128 * t;
        int r = idx >> 3, u = idx & 7;
        cp16(kd + (r * KSTR + u * 8) * 2, ksrc + r * 64 + u * 8);
        cp16(kd + 9216 + (r * KSTR + u * 8) * 2, vsrc + r * 64 + u * 8);
    }
}

__global__ __launch_bounds__(128) void attn_mma(const float* __restrict__ mWin) {
    extern __shared__ char smem[];
    float* bias_s = (float*)(smem + 9216);

    const int tid = threadIdx.x;
    const int lane = tid & 31, w = tid >> 5;
    const int qt = blockIdx.x & 31;
    const int bh = blockIdx.x >> 5;
    const int b = bh >> 4, h = bh & 15;

    const __half* qh_g = g_qh + ((size_t)bh * 2048 + qt * 64) * 64;
    const __half* kf_g = g_kf + (size_t)bh * 2048 * 64;
    const __half* vf_g = g_vf + (size_t)bh * 2048 * 64;

    const uint32_t sbase = smem_u32(smem);

    // issue cp.async for key tile 0
    stage_kv(sbase + SM_KV0, kf_g, vf_g, tid);
    asm volatile("cp.async.commit_group;" ::: "memory");

    // stage Q (64 rows x 64 halves, stride 72)
#pragma unroll
    for (int t = 0; t < 4; t++) {
        int idx = tid + 128 * t;
        int r = idx >> 3, u = idx & 7;
        *(uint4*)(smem + ((size_t)r * QSTR + u * 8) * 2) =
            *(const uint4*)(qh_g + r * 64 + u * 8);
    }
    __syncthreads();

    // preload Q fragments (4 k-chunks x 4 regs)
    uint32_t aQ[4][4];
#pragma unroll
    for (int kc = 0; kc < 4; kc++) {
        uint32_t addr = sbase +
            ((w * 16 + (lane & 15)) * QSTR + kc * 16 + (lane >> 4) * 8) * 2;
        ldsm_x4(addr, aQ[kc][0], aQ[kc][1], aQ[kc][2], aQ[kc][3]);
    }

    // ldmatrix relative offsets
    uint32_t kb_rel[4], vb_rel[4];
#pragma unroll
    for (int p = 0; p < 4; p++)
        kb_rel[p] = ((p * 16 + ((lane >> 4) << 3) + (lane & 7)) * KSTR +
                     (((lane >> 3) & 1) << 3)) * 2;
#pragma unroll
    for (int dn = 0; dn < 4; dn++)
        vb_rel[dn] = ((((lane >> 3) & 1) * 8 + (lane & 7)) * KSTR +
                      dn * 16 + (lane >> 4) * 8) * 2;

    float accO[8][4] = {};
    float m_lo = -1e30f, m_hi = -1e30f, l_lo = 0.0f, l_hi = 0.0f;
    const int c2 = (lane & 3) * 2;

    for (int kt = 0; kt < 32; kt++) {
        const int buf = kt & 1;
        if (kt + 1 < 32) {
            stage_kv(sbase + SM_KV0 + (buf ^ 1) * KVBUF,
                     kf_g + (size_t)(kt + 1) * 64 * 64,
                     vf_g + (size_t)(kt + 1) * 64 * 64, tid);
            asm volatile("cp.async.commit_group;" ::: "memory");
            asm volatile("cp.async.wait_group 1;" ::: "memory");
        } else {
            asm volatile("cp.async.wait_group 0;" ::: "memory");
        }
        if (tid < 64)
            bias_s[tid] = (mWin[b * 2048 + kt * 64 + tid] * 100.0f - 100.0f) * LOG2E;
        __syncthreads();

        const uint32_t kbase = sbase + SM_KV0 + buf * KVBUF;
        const uint32_t vbase = kbase + 9216;

        // S = Q*K (single fp16 pass)
        float accS[8][4] = {};
#pragma unroll
        for (int dc = 0; dc < 4; dc++) {
#pragma unroll
            for (int p = 0; p < 4; p++) {
                uint32_t b0, b1, b2, b3;
                ldsm_x4(kbase + kb_rel[p] + dc * 32, b0, b1, b2, b3);
                uint32_t bb[2];
                bb[0] = b0; bb[1] = b1;
                mma_f16(accS[2 * p], aQ[dc], bb);
                bb[0] = b2; bb[1] = b3;
                mma_f16(accS[2 * p + 1], aQ[dc], bb);
            }
        }

        // + key bias (log2 units)
#pragma unroll
        for (int j = 0; j < 8; j++) {
            float b0v = bias_s[8 * j + c2], b1v = bias_s[8 * j + c2 + 1];
            accS[j][0] += b0v; accS[j][1] += b1v;
            accS[j][2] += b0v; accS[j][3] += b1v;
        }

        // online softmax (rows r=lane>>2 and r+8)
        float mx0 = -1e30f, mx1 = -1e30f;
#pragma unroll
        for (int j = 0; j < 8; j++) {
            mx0 = fmaxf(mx0, fmaxf(accS[j][0], accS[j][1]));
            mx1 = fmaxf(mx1, fmaxf(accS[j][2], accS[j][3]));
        }
        mx0 = fmaxf(mx0, __shfl_xor_sync(0xffffffffu, mx0, 1));
        mx0 = fmaxf(mx0, __shfl_xor_sync(0xffffffffu, mx0, 2));
        mx1 = fmaxf(mx1, __shfl_xor_sync(0xffffffffu, mx1, 1));
        mx1 = fmaxf(mx1, __shfl_xor_sync(0xffffffffu, mx1, 2));
        float mn0 = fmaxf(m_lo, mx0), mn1 = fmaxf(m_hi, mx1);
        float cor0 = exp2_poly(m_lo - mn0), cor1 = exp2_poly(m_hi - mn1);
        m_lo = mn0; m_hi = mn1;

        float s0 = 0.0f, s1 = 0.0f;
#pragma unroll
        for (int j = 0; j < 8; j++) {
            accS[j][0] = exp2_poly(accS[j][0] - m_lo);
            accS[j][1] = exp2_poly(accS[j][1] - m_lo);
            accS[j][2] = exp2_poly(accS[j][2] - m_hi);
            accS[j][3] = exp2_poly(accS[j][3] - m_hi);
            s0 += accS[j][0] + accS[j][1];
            s1 += accS[j][2] + accS[j][3];
        }
        s0 += __shfl_xor_sync(0xffffffffu, s0, 1);
        s0 += __shfl_xor_sync(0xffffffffu, s0, 2);
        s1 += __shfl_xor_sync(0xffffffffu, s1, 1);
        s1 += __shfl_xor_sync(0xffffffffu, s1, 2);
        l_lo = l_lo * cor0 + s0;
        l_hi = l_hi * cor1 + s1;
#pragma unroll
        for (int j = 0; j < 8; j++) {
            accO[j][0] *= cor0; accO[j][1] *= cor0;
            accO[j][2] *= cor1; accO[j][3] *= cor1;
        }

        // pack P -> fp16 A-fragments (in registers)
        uint32_t ph[8][2];
#pragma unroll
        for (int j = 0; j < 8; j++) {
            ph[j][0] = pack_h2(accS[j][0], accS[j][1]);
            ph[j][1] = pack_h2(accS[j][2], accS[j][3]);
        }

        // O += P * V  (V via ldmatrix.trans)
#pragma unroll
        for (int kc = 0; kc < 4; kc++) {
            uint32_t a[4] = {ph[2 * kc][0], ph[2 * kc][1],
                             ph[2 * kc + 1][0], ph[2 * kc + 1][1]};
#pragma unroll
            for (int dn = 0; dn < 4; dn++) {
                uint32_t r0, r1, r2, r3;
                ldsm_x4_t(vbase + vb_rel[dn] + kc * 16 * KSTR * 2, r0, r1, r2, r3);
                uint32_t bb[2];
                bb[0] = r0; bb[1] = r1;
                mma_f16(accO[2 * dn], a, bb);
                bb[0] = r2; bb[1] = r3;
                mma_f16(accO[2 * dn + 1], a, bb);
            }
        }
        __syncthreads();
    }

    // epilogue: O / l -> fp16, into proj GEMM A input g_of[token][h*64+d]
    float i0 = 1.0f / l_lo, i1 = 1.0f / l_hi;
    int qn = qt * 64 + w * 16 + (lane >> 2);
    int col0 = h * 64 + c2;
#pragma unroll
    for (int j = 0; j < 8; j++) {
        size_t off0 = (size_t)(b * 2048 + qn) * 1024 + col0 + 8 * j;
        size_t off1 = (size_t)(b * 2048 + qn + 8) * 1024 + col0 + 8 * j;
        *(__half2*)(g_of + off0) = __floats2half2_rn(accO[j][0] * i0,
                                                     accO[j][1] * i0);
        *(__half2*)(g_of + off1) = __floats2half2_rn(accO[j][2] * i1,
                                                     accO[j][3] * i1);
    }
}

// ---------------------------------------------------------------------------
extern "C" void kernel_launch(void* const* d_in, const int* in_sizes, int n_in,
                              void* d_out, int out_size) {
    const float* x      = (const float*)d_in[0];
    const float* mWin   = (const float*)d_in[1];
    const float* w_qkv  = (const float*)d_in[2];
    const float* w_proj = (const float*)d_in[3];
    const float* b_proj = (const float*)d_in[4];
    float* out = (float*)d_out;

    __half *xh, *wqh, *wph, *wpl, *of;
    cudaGetSymbolAddress((void**)&xh,  g_xh);
    cudaGetSymbolAddress((void**)&wqh, g_wqh);
    cudaGetSymbolAddress((void**)&wph, g_wph);
    cudaGetSymbolAddress((void**)&wpl, g_wpl);
    cudaGetSymbolAddress((void**)&of,  g_of);

    cudaFuncSetAttribute(gemm_mma, cudaFuncAttributeMaxDynamicSharedMemorySize,
                         GEMM_SMEM_BYTES);
    cudaFuncSetAttribute(attn_mma, cudaFuncAttributeMaxDynamicSharedMemorySize,
                         ATTN_SMEM_BYTES);

    // Conversions
    tofp16_kernel<<<8192, 256>>>(x, xh);
    tofp16_kernel<<<3072, 256>>>(w_qkv, wqh);
    splitf16_kernel<<<1024, 256>>>(w_proj, wph, wpl);

    // QKV projection (fp16 SINGLE pass — outputs are fp16-rounded anyway)
    gemm_mma<<<dim3(24, 64), 256, GEMM_SMEM_BYTES>>>(xh, wqh, nullptr,
                                                     nullptr, nullptr, 0);

    // Flash attention (mma.sync fp16), writes g_of
    attn_mma<<<2048, 128, ATTN_SMEM_BYTES>>>(mWin);

    // Output projection (fp16 2-pass: final fp32 output, keep the Wl term)
    gemm_mma<<<dim3(8, 64), 256, GEMM_SMEM_BYTES>>>(of, wph, wpl,
                                                    b_proj, out, 1);
}